// round 1
// baseline (speedup 1.0000x reference)
#include <cuda_runtime.h>
#include <math.h>

// Problem constants
#define NB 8
#define NC 128
#define NH 128
#define NWD 128
#define NHW 16384
#define NE 4
#define NR 64

// Main-kernel smem tiling
#define XPAD 68    // 64-col tiles padded to 68 (16B-aligned rows, conflict-free f4)
#define WPAD 129   // 128-wide weight rows padded to 129 (conflict-free k-major)
#define SMEM_MAIN ((3 * 128 * XPAD + 128 * WPAD) * 4)   // 170496 bytes

// Device scratch (no allocations allowed)
__device__ float g_fe0[NB * NC];
__device__ float g_pooled[NB * NC];
__device__ int   g_sel[NB * 2];
__device__ float g_gate[NB * 2];
__device__ float g_gsum[NB];
__device__ float g_PW2[NE * NC * NR];   // proj_w @ exp_w2[e] : [e][d][r]

__device__ __forceinline__ float gelu_f(float v) {
    return 0.5f * v * (1.0f + erff(v * 0.70710678118654752440f));
}

// ---------------------------------------------------------------------------
// Kernel 1: per-(b,c) plane: depthwise 3x3 high-pass -> GELU -> mean  (g_fe0)
//           and raw mean (g_pooled). Plane staged in smem (64 KB dynamic).
// ---------------------------------------------------------------------------
__global__ __launch_bounds__(256) void conv_pool_kernel(const float* __restrict__ x) {
    extern __shared__ float sp[];                 // 16384 floats
    const int t = threadIdx.x;
    const float* xp = x + (size_t)blockIdx.x * NHW;

    float sumx = 0.f;
    #pragma unroll 4
    for (int i = 0; i < 16; ++i) {                // 4096 float4 total
        int i4 = t + (i << 8);
        float4 v = ((const float4*)xp)[i4];
        ((float4*)sp)[i4] = v;
        sumx += v.x + v.y + v.z + v.w;
    }
    __syncthreads();

    float sumg = 0.f;
    #pragma unroll 4
    for (int i = 0; i < 64; ++i) {
        int idx = t + (i << 8);
        int h = idx >> 7, w = idx & 127;
        float cen = sp[idx];
        float nb = 0.f;
        bool up = (h > 0), dn = (h < 127), lf = (w > 0), rt = (w < 127);
        if (up)        nb += sp[idx - 128];
        if (dn)        nb += sp[idx + 128];
        if (lf)        nb += sp[idx - 1];
        if (rt)        nb += sp[idx + 1];
        if (up && lf)  nb += sp[idx - 129];
        if (up && rt)  nb += sp[idx - 127];
        if (dn && lf)  nb += sp[idx + 127];
        if (dn && rt)  nb += sp[idx + 129];
        sumg += gelu_f(8.f * cen - nb);           // hp kernel: center 8, ring -1
    }

    __shared__ float rx[8], rg[8];
    for (int o = 16; o > 0; o >>= 1) {
        sumx += __shfl_down_sync(0xffffffffu, sumx, o);
        sumg += __shfl_down_sync(0xffffffffu, sumg, o);
    }
    if ((t & 31) == 0) { rx[t >> 5] = sumx; rg[t >> 5] = sumg; }
    __syncthreads();
    if (t == 0) {
        float ax = 0.f, ag = 0.f;
        #pragma unroll
        for (int i = 0; i < 8; ++i) { ax += rx[i]; ag += rg[i]; }
        const float inv = 1.0f / 16384.0f;
        g_pooled[blockIdx.x] = ax * inv;
        g_fe0[blockIdx.x]   = ag * inv;
    }
}

// ---------------------------------------------------------------------------
// Kernel 2: MLP on fe0, routing logits, softmax, top-2 -> g_sel/g_gate/g_gsum
// ---------------------------------------------------------------------------
__global__ __launch_bounds__(256) void routing_kernel(
    const float* __restrict__ mlp_w1, const float* __restrict__ mlp_b1,
    const float* __restrict__ mlp_w2, const float* __restrict__ mlp_b2,
    const float* __restrict__ gate_w, const float* __restrict__ fgate_w) {
    __shared__ float s_fe0[NB * NC];
    __shared__ float s_pool[NB * NC];
    __shared__ float s_h1[NB * 256];
    __shared__ float s_fe[NB * NC];
    __shared__ float s_log[NB * NE];
    const int t = threadIdx.x;

    for (int i = t; i < NB * NC; i += 256) { s_fe0[i] = g_fe0[i]; s_pool[i] = g_pooled[i]; }
    __syncthreads();

    // h1 = gelu(fe0 @ mlp_w1 + b1)   [8, 256]
    #pragma unroll
    for (int o = 0; o < 8; ++o) {
        int idx = (o << 8) + t; int b = idx >> 8; int j = idx & 255;
        float a = mlp_b1[j];
        const float* f = s_fe0 + b * NC;
        for (int c = 0; c < NC; ++c) a += f[c] * mlp_w1[c * 256 + j];
        s_h1[idx] = gelu_f(a);
    }
    __syncthreads();

    // fe = h1 @ mlp_w2 + b2   [8, 128]
    #pragma unroll
    for (int o = 0; o < 4; ++o) {
        int idx = (o << 8) + t; int b = idx >> 7; int d = idx & 127;
        float a = mlp_b2[d];
        const float* h = s_h1 + b * 256;
        for (int c = 0; c < 256; ++c) a += h[c] * mlp_w2[c * NC + d];
        s_fe[idx] = a;
    }
    __syncthreads();

    // logits = pooled@gate_w + fe@freq_gate_w   [8, 4]
    if (t < NB * NE) {
        int b = t >> 2, e = t & 3;
        float a = 0.f;
        for (int c = 0; c < NC; ++c)
            a += s_pool[b * NC + c] * gate_w[c * NE + e] + s_fe[b * NC + c] * fgate_w[c * NE + e];
        s_log[t] = a;
    }
    __syncthreads();

    // softmax + top-2 (strict > keeps lowest index on ties, matching jax top_k)
    if (t < NB) {
        float sc[NE];
        float m = -1e30f;
        #pragma unroll
        for (int e = 0; e < NE; ++e) { sc[e] = s_log[t * NE + e]; m = fmaxf(m, sc[e]); }
        float ss = 0.f;
        #pragma unroll
        for (int e = 0; e < NE; ++e) { sc[e] = expf(sc[e] - m); ss += sc[e]; }
        float inv = 1.0f / ss;
        #pragma unroll
        for (int e = 0; e < NE; ++e) sc[e] *= inv;
        int i0 = 0;
        #pragma unroll
        for (int e = 1; e < NE; ++e) if (sc[e] > sc[i0]) i0 = e;
        int i1 = -1;
        #pragma unroll
        for (int e = 0; e < NE; ++e) {
            if (e == i0) continue;
            if (i1 < 0 || sc[e] > sc[i1]) i1 = e;
        }
        g_sel[t * 2] = i0;  g_sel[t * 2 + 1] = i1;
        g_gate[t * 2] = sc[i0]; g_gate[t * 2 + 1] = sc[i1];
        g_gsum[t] = sc[i0] + sc[i1];
    }
}

// ---------------------------------------------------------------------------
// Kernel 3: PW2[e][d][r] = sum_c proj_w[d][c] * exp_w2[e][c][r]
// ---------------------------------------------------------------------------
__global__ __launch_bounds__(256) void pw2_kernel(const float* __restrict__ exp_w2,
                                                  const float* __restrict__ proj_w) {
    int e = blockIdx.x >> 5;
    int d = ((blockIdx.x & 31) << 2) + (threadIdx.x >> 6);
    int r = threadIdx.x & 63;
    const float* pw = proj_w + d * NC;
    const float* w2 = exp_w2 + (size_t)e * NC * NR + r;
    float a = 0.f;
    #pragma unroll 8
    for (int c = 0; c < NC; ++c) a += pw[c] * w2[c * NR];
    g_PW2[(e * NC + d) * NR + r] = a;
}

// ---------------------------------------------------------------------------
// Main fused kernel.  Per block: batch b, 64 consecutive pixels.
//   T0 = (W0[e0]@x) * silu(W1[e0]@sh),  T1 = same for e1   (stacked in sT)
//   out = [g0*PW2[e0] | g1*PW2[e1]] @ [T0;T1] + gsum*proj @ x
// 256 threads, thread tile 8(M) x 4(N), four K=128 GEMM phases.
// ---------------------------------------------------------------------------
__device__ __forceinline__ void gemm_k128(const float* __restrict__ sW,
                                          const float* __restrict__ sB,
                                          float acc[8][4], int tm8, int tn4) {
    #pragma unroll 8
    for (int k = 0; k < 128; ++k) {
        const float* wr = sW + k * WPAD + tm8;
        float4 bv = *(const float4*)(sB + k * XPAD + tn4);
        #pragma unroll
        for (int i = 0; i < 8; ++i) {
            float w = wr[i];
            acc[i][0] += w * bv.x;
            acc[i][1] += w * bv.y;
            acc[i][2] += w * bv.z;
            acc[i][3] += w * bv.w;
        }
    }
}

__global__ __launch_bounds__(256, 1) void main_kernel(
    const float* __restrict__ x, const float* __restrict__ sh,
    const float* __restrict__ exp_w0, const float* __restrict__ exp_w1,
    const float* __restrict__ proj_w, float* __restrict__ out) {
    extern __shared__ float smem[];
    float* sX = smem;                    // [128][XPAD]
    float* sS = sX + 128 * XPAD;         // [128][XPAD]
    float* sT = sS + 128 * XPAD;         // [128][XPAD]
    float* sW = sT + 128 * XPAD;         // [128][WPAD]  k-major weights

    const int t   = threadIdx.x;
    const int b   = blockIdx.y;
    const int hw0 = blockIdx.x * 64;
    const int tm8 = (t >> 4) << 3;
    const int tn4 = (t & 15) << 2;

    const int   e0  = g_sel[b * 2],  e1  = g_sel[b * 2 + 1];
    const float ga0 = g_gate[b * 2], ga1 = g_gate[b * 2 + 1];
    const float gs  = g_gsum[b];

    const float* xb = x  + (size_t)b * NC * NHW + hw0;
    const float* sb = sh + (size_t)b * NC * NHW + hw0;

    // ---- stage x tile, shared tile, Wcat0 = [W0[e0]; W0[e1]] (k-major) ----
    #pragma unroll
    for (int i = 0; i < 8; ++i) {
        int idx = t + (i << 8);
        int c = idx >> 4; int n4 = (idx & 15) << 2;
        *(float4*)&sX[c * XPAD + n4] = *(const float4*)(xb + (size_t)c * NHW + n4);
        *(float4*)&sS[c * XPAD + n4] = *(const float4*)(sb + (size_t)c * NHW + n4);
    }
    {
        const float* wa = exp_w0 + (size_t)e0 * NR * NC;
        const float* wb = exp_w0 + (size_t)e1 * NR * NC;
        #pragma unroll 8
        for (int i = 0; i < 64; ++i) {
            int idx = t + (i << 8); int m = idx >> 7; int k = idx & 127;
            float v = (m < 64) ? wa[m * NC + k] : wb[(m - 64) * NC + k];
            sW[k * WPAD + m] = v;
        }
    }
    __syncthreads();

    // ---- GEMM 1: accA = Wcat0 @ x_tile ----
    float accA[8][4];
    #pragma unroll
    for (int i = 0; i < 8; ++i)
        #pragma unroll
        for (int j = 0; j < 4; ++j) accA[i][j] = 0.f;
    gemm_k128(sW, sX, accA, tm8, tn4);
    __syncthreads();

    // ---- stage Wcat1 = [W1[e0]; W1[e1]] ----
    {
        const float* wa = exp_w1 + (size_t)e0 * NR * NC;
        const float* wb = exp_w1 + (size_t)e1 * NR * NC;
        #pragma unroll 8
        for (int i = 0; i < 64; ++i) {
            int idx = t + (i << 8); int m = idx >> 7; int k = idx & 127;
            float v = (m < 64) ? wa[m * NC + k] : wb[(m - 64) * NC + k];
            sW[k * WPAD + m] = v;
        }
    }
    __syncthreads();

    // ---- GEMM 2: accG = Wcat1 @ sh_tile ----
    float accG[8][4];
    #pragma unroll
    for (int i = 0; i < 8; ++i)
        #pragma unroll
        for (int j = 0; j < 4; ++j) accG[i][j] = 0.f;
    gemm_k128(sW, sS, accG, tm8, tn4);

    // ---- T = accA * silu(accG) -> sT (k-major for GEMM 3) ----
    #pragma unroll
    for (int i = 0; i < 8; ++i) {
        float4 tv;
        float u;
        u = accG[i][0]; tv.x = accA[i][0] * (u / (1.f + __expf(-u)));
        u = accG[i][1]; tv.y = accA[i][1] * (u / (1.f + __expf(-u)));
        u = accG[i][2]; tv.z = accA[i][2] * (u / (1.f + __expf(-u)));
        u = accG[i][3]; tv.w = accA[i][3] * (u / (1.f + __expf(-u)));
        *(float4*)&sT[(tm8 + i) * XPAD + tn4] = tv;
    }
    __syncthreads();  // sT ready, sW free

    // ---- stage Mcat = [g0*PW2[e0] | g1*PW2[e1]] (k = stacked rank) ----
    {
        const float* p0 = g_PW2 + (size_t)e0 * NC * NR;
        const float* p1 = g_PW2 + (size_t)e1 * NC * NR;
        #pragma unroll 8
        for (int i = 0; i < 64; ++i) {
            int idx = t + (i << 8); int d = idx >> 7; int r = idx & 127;
            float v = (r < 64) ? ga0 * p0[d * NR + r] : ga1 * p1[d * NR + (r - 64)];
            sW[r * WPAD + d] = v;
        }
    }
    __syncthreads();

    // ---- GEMM 3: acc2 = Mcat @ sT ----
    float acc2[8][4];
    #pragma unroll
    for (int i = 0; i < 8; ++i)
        #pragma unroll
        for (int j = 0; j < 4; ++j) acc2[i][j] = 0.f;
    gemm_k128(sW, sT, acc2, tm8, tn4);
    __syncthreads();

    // ---- stage gsum * proj_w (k = input channel) ----
    #pragma unroll 8
    for (int i = 0; i < 64; ++i) {
        int idx = t + (i << 8); int d = idx >> 7; int c = idx & 127;
        sW[c * WPAD + d] = gs * proj_w[d * NC + c];
    }
    __syncthreads();

    // ---- GEMM 4: acc2 += (gsum*proj) @ x_tile ----
    gemm_k128(sW, sX, acc2, tm8, tn4);

    // ---- write output tile ----
    float* ob = out + (size_t)b * NC * NHW + hw0;
    #pragma unroll
    for (int i = 0; i < 8; ++i) {
        float4 o = make_float4(acc2[i][0], acc2[i][1], acc2[i][2], acc2[i][3]);
        *(float4*)(ob + (size_t)(tm8 + i) * NHW + tn4) = o;
    }
}

// ---------------------------------------------------------------------------
extern "C" void kernel_launch(void* const* d_in, const int* in_sizes, int n_in,
                              void* d_out, int out_size) {
    const float* x       = (const float*)d_in[0];
    const float* sh      = (const float*)d_in[1];
    const float* mlp_w1  = (const float*)d_in[2];
    const float* mlp_b1  = (const float*)d_in[3];
    const float* mlp_w2  = (const float*)d_in[4];
    const float* mlp_b2  = (const float*)d_in[5];
    const float* gate_w  = (const float*)d_in[6];
    const float* fgate_w = (const float*)d_in[7];
    const float* exp_w0  = (const float*)d_in[8];
    const float* exp_w1  = (const float*)d_in[9];
    const float* exp_w2  = (const float*)d_in[10];
    const float* proj_w  = (const float*)d_in[11];
    float* out = (float*)d_out;

    cudaFuncSetAttribute(conv_pool_kernel, cudaFuncAttributeMaxDynamicSharedMemorySize, 65536);
    cudaFuncSetAttribute(main_kernel, cudaFuncAttributeMaxDynamicSharedMemorySize, SMEM_MAIN);

    conv_pool_kernel<<<NB * NC, 256, 65536>>>(x);
    routing_kernel<<<1, 256>>>(mlp_w1, mlp_b1, mlp_w2, mlp_b2, gate_w, fgate_w);
    pw2_kernel<<<128, 256>>>(exp_w2, proj_w);
    main_kernel<<<dim3(NHW / 64, NB), 256, SMEM_MAIN>>>(x, sh, exp_w0, exp_w1, proj_w, out);
}

// round 3
// speedup vs baseline: 3.8257x; 3.8257x over previous
#include <cuda_runtime.h>
#include <math.h>
#include <stdint.h>

// Problem constants
#define NB 8
#define NC 128
#define NHW 16384
#define NE 4
#define NR 64

// smem layout (words) for main kernel
#define LDW 132           // weight tile ld  (132 % 32 == 4 -> bank 4m+k, conflict-free)
#define LDX 136           // act tile ld     (136 % 32 == 8 -> bank 8k+n, conflict-free)
#define SM_X 0
#define SM_S (128 * LDX)
#define SM_W (2 * 128 * LDX)
#define SMEM_MAIN ((2 * 128 * LDX + 128 * LDW) * 4)   // 206848 bytes

// ---------------- device scratch ----------------
__device__ float g_fe0[NB * NC];
__device__ float g_pooled[NB * NC];
__device__ int   g_sel[NB * 2];
__device__ float g_gate[NB * 2];
__device__ float g_gsum[NB];
__device__ float g_PW2[NE * NC * NR];   // proj_w @ exp_w2[e] : [e][d][r]

__device__ __forceinline__ float gelu_f(float v) {
    return 0.5f * v * (1.0f + erff(v * 0.70710678118654752440f));
}
__device__ __forceinline__ uint32_t f2tf(float f) {
    uint32_t r; asm("cvt.rna.tf32.f32 %0, %1;" : "=r"(r) : "f"(f)); return r;
}
__device__ __forceinline__ void mma_tf32(float* c, const uint32_t* a, const uint32_t* b) {
    asm volatile(
        "mma.sync.aligned.m16n8k8.row.col.f32.tf32.tf32.f32 "
        "{%0,%1,%2,%3}, {%4,%5,%6,%7}, {%8,%9}, {%0,%1,%2,%3};"
        : "+f"(c[0]), "+f"(c[1]), "+f"(c[2]), "+f"(c[3])
        : "r"(a[0]), "r"(a[1]), "r"(a[2]), "r"(a[3]), "r"(b[0]), "r"(b[1]));
}

// ---------------------------------------------------------------------------
// Kernel 1: per-(b,c) plane: depthwise 3x3 high-pass -> GELU -> mean + raw mean
// ---------------------------------------------------------------------------
__global__ __launch_bounds__(256) void conv_pool_kernel(const float* __restrict__ x) {
    extern __shared__ float sp[];
    const int t = threadIdx.x;
    const float* xp = x + (size_t)blockIdx.x * NHW;

    float sumx = 0.f;
    #pragma unroll 4
    for (int i = 0; i < 16; ++i) {
        int i4 = t + (i << 8);
        float4 v = ((const float4*)xp)[i4];
        ((float4*)sp)[i4] = v;
        sumx += v.x + v.y + v.z + v.w;
    }
    __syncthreads();

    float sumg = 0.f;
    #pragma unroll 4
    for (int i = 0; i < 64; ++i) {
        int idx = t + (i << 8);
        int h = idx >> 7, w = idx & 127;
        float cen = sp[idx];
        float nb = 0.f;
        bool up = (h > 0), dn = (h < 127), lf = (w > 0), rt = (w < 127);
        if (up)        nb += sp[idx - 128];
        if (dn)        nb += sp[idx + 128];
        if (lf)        nb += sp[idx - 1];
        if (rt)        nb += sp[idx + 1];
        if (up && lf)  nb += sp[idx - 129];
        if (up && rt)  nb += sp[idx - 127];
        if (dn && lf)  nb += sp[idx + 127];
        if (dn && rt)  nb += sp[idx + 129];
        sumg += gelu_f(8.f * cen - nb);
    }

    __shared__ float rx[8], rg[8];
    for (int o = 16; o > 0; o >>= 1) {
        sumx += __shfl_down_sync(0xffffffffu, sumx, o);
        sumg += __shfl_down_sync(0xffffffffu, sumg, o);
    }
    if ((t & 31) == 0) { rx[t >> 5] = sumx; rg[t >> 5] = sumg; }
    __syncthreads();
    if (t == 0) {
        float ax = 0.f, ag = 0.f;
        #pragma unroll
        for (int i = 0; i < 8; ++i) { ax += rx[i]; ag += rg[i]; }
        const float inv = 1.0f / 16384.0f;
        g_pooled[blockIdx.x] = ax * inv;
        g_fe0[blockIdx.x]   = ag * inv;
    }
}

// ---------------------------------------------------------------------------
// Kernel 2: routing, one block per batch
// ---------------------------------------------------------------------------
__global__ __launch_bounds__(256) void routing_kernel(
    const float* __restrict__ mlp_w1, const float* __restrict__ mlp_b1,
    const float* __restrict__ mlp_w2, const float* __restrict__ mlp_b2,
    const float* __restrict__ gate_w, const float* __restrict__ fgate_w) {
    __shared__ float s_in[NC], s_pool[NC], s_h1[256], s_fe[NC], s_log[NE];
    const int b = blockIdx.x;
    const int t = threadIdx.x;

    if (t < NC) { s_in[t] = g_fe0[b * NC + t]; s_pool[t] = g_pooled[b * NC + t]; }
    __syncthreads();

    {
        float a = mlp_b1[t];
        #pragma unroll 8
        for (int c = 0; c < NC; ++c) a += s_in[c] * mlp_w1[c * 256 + t];
        s_h1[t] = gelu_f(a);
    }
    __syncthreads();
    if (t < NC) {
        float a = mlp_b2[t];
        #pragma unroll 8
        for (int c = 0; c < 256; ++c) a += s_h1[c] * mlp_w2[c * NC + t];
        s_fe[t] = a;
    }
    __syncthreads();
    if (t < NE) {
        float a = 0.f;
        for (int c = 0; c < NC; ++c)
            a += s_pool[c] * gate_w[c * NE + t] + s_fe[c] * fgate_w[c * NE + t];
        s_log[t] = a;
    }
    __syncthreads();
    if (t == 0) {
        float sc[NE];
        float m = -1e30f;
        #pragma unroll
        for (int e = 0; e < NE; ++e) { sc[e] = s_log[e]; m = fmaxf(m, sc[e]); }
        float ss = 0.f;
        #pragma unroll
        for (int e = 0; e < NE; ++e) { sc[e] = expf(sc[e] - m); ss += sc[e]; }
        float inv = 1.0f / ss;
        #pragma unroll
        for (int e = 0; e < NE; ++e) sc[e] *= inv;
        int i0 = 0;
        #pragma unroll
        for (int e = 1; e < NE; ++e) if (sc[e] > sc[i0]) i0 = e;
        int i1 = -1;
        #pragma unroll
        for (int e = 0; e < NE; ++e) {
            if (e == i0) continue;
            if (i1 < 0 || sc[e] > sc[i1]) i1 = e;
        }
        g_sel[b * 2] = i0;  g_sel[b * 2 + 1] = i1;
        g_gate[b * 2] = sc[i0]; g_gate[b * 2 + 1] = sc[i1];
        g_gsum[b] = sc[i0] + sc[i1];
    }
}

// ---------------------------------------------------------------------------
// Kernel 3: PW2[e][d][r] = sum_c proj_w[d][c] * exp_w2[e][c][r]
// ---------------------------------------------------------------------------
__global__ __launch_bounds__(256) void pw2_kernel(const float* __restrict__ exp_w2,
                                                  const float* __restrict__ proj_w) {
    int e = blockIdx.x >> 5;
    int d = ((blockIdx.x & 31) << 2) + (threadIdx.x >> 6);
    int r = threadIdx.x & 63;
    const float* pw = proj_w + d * NC;
    const float* w2 = exp_w2 + (size_t)e * NC * NR + r;
    float a = 0.f;
    #pragma unroll 8
    for (int c = 0; c < NC; ++c) a += pw[c] * w2[c * NR];
    g_PW2[(e * NC + d) * NR + r] = a;
}

// ---------------------------------------------------------------------------
// Main tensor-core kernel (mma.sync tf32).  One block = (batch, 128 pixels).
// ---------------------------------------------------------------------------

// stage [128m][128k] row-major tf32 weight tile; rows 0..63 from a, 64..127 from b2
__device__ __forceinline__ void stage_w_cat(uint32_t* sW, const float* __restrict__ a,
                                            const float* __restrict__ b2, float sc, int t) {
    #pragma unroll
    for (int f = t; f < 4096; f += 256) {
        int row = f >> 5, q = f & 31;
        const float* src = (row < 64) ? (a + row * 128 + q * 4)
                                      : (b2 + (row - 64) * 128 + q * 4);
        float4 u = *(const float4*)src;
        uint4 w;
        w.x = f2tf(u.x * sc); w.y = f2tf(u.y * sc);
        w.z = f2tf(u.z * sc); w.w = f2tf(u.w * sc);
        *(uint4*)(sW + row * LDW + q * 4) = w;
    }
}

// stage Mcat[d][k]: k<64 -> ga0*PW2[e0][d][k] ; k>=64 -> ga1*PW2[e1][d][k-64]
__device__ __forceinline__ void stage_mcat(uint32_t* sW, const float* __restrict__ pw2,
                                           int e0, int e1, float ga0, float ga1, int t) {
    #pragma unroll
    for (int f = t; f < 4096; f += 256) {
        int row = f >> 5, q = f & 31;
        int lo = (q < 16);
        const float* src = pw2 + ((size_t)(lo ? e0 : e1) * NC + row) * NR + (q & 15) * 4;
        float sc = lo ? ga0 : ga1;
        float4 u = *(const float4*)src;
        uint4 w;
        w.x = f2tf(u.x * sc); w.y = f2tf(u.y * sc);
        w.z = f2tf(u.z * sc); w.w = f2tf(u.w * sc);
        *(uint4*)(sW + row * LDW + q * 4) = w;
    }
}

// stage [128k][128n] activation tile (k = channel, n = pixel)
__device__ __forceinline__ void stage_act(uint32_t* sA, const float* __restrict__ gsrc, int t) {
    #pragma unroll
    for (int f = t; f < 4096; f += 256) {
        int c = f >> 5, q = f & 31;
        float4 u = *(const float4*)(gsrc + (size_t)c * NHW + q * 4);
        uint4 w;
        w.x = f2tf(u.x); w.y = f2tf(u.y); w.z = f2tf(u.z); w.w = f2tf(u.w);
        *(uint4*)(sA + c * LDX + q * 4) = w;
    }
}

// acc[mf][nf][4] += sW[m0+.., k] * sB[k, n0+..]   (M=32, N=64, K=128)
__device__ __forceinline__ void gemm_mma(const uint32_t* __restrict__ sW,
                                         const uint32_t* __restrict__ sB,
                                         float acc[2][8][4], int m0, int n0, int lane) {
    const int ar = lane >> 2, ac = lane & 3;
    #pragma unroll
    for (int kk = 0; kk < 16; ++kk) {
        const int k0 = kk << 3;
        uint32_t a[2][4];
        #pragma unroll
        for (int mf = 0; mf < 2; ++mf) {
            const uint32_t* pa = sW + (m0 + mf * 16 + ar) * LDW + k0 + ac;
            a[mf][0] = pa[0];
            a[mf][2] = pa[4];
            a[mf][1] = pa[8 * LDW];
            a[mf][3] = pa[8 * LDW + 4];
        }
        #pragma unroll
        for (int nf = 0; nf < 8; ++nf) {
            const uint32_t* pb = sB + (k0 + ac) * LDX + n0 + nf * 8 + ar;
            uint32_t b[2];
            b[0] = pb[0];
            b[1] = pb[4 * LDX];
            mma_tf32(acc[0][nf], a[0], b);
            mma_tf32(acc[1][nf], a[1], b);
        }
    }
}

__global__ __launch_bounds__(256, 1) void main_mma_kernel(
    const float* __restrict__ x, const float* __restrict__ sh,
    const float* __restrict__ exp_w0, const float* __restrict__ exp_w1,
    const float* __restrict__ proj_w, float* __restrict__ out) {
    extern __shared__ uint32_t smem[];
    uint32_t* sX = smem + SM_X;
    uint32_t* sS = smem + SM_S;     // later reused for T
    uint32_t* sW = smem + SM_W;

    const int t = threadIdx.x;
    const int lane = t & 31;
    const int wid = t >> 5;
    const int m0 = (wid >> 1) << 5;          // 0,32,64,96
    const int n0 = (wid & 1) << 6;           // 0,64
    const int b = blockIdx.y;
    const int hw0 = blockIdx.x * 128;

    const int   e0  = g_sel[b * 2],  e1  = g_sel[b * 2 + 1];
    const float ga0 = g_gate[b * 2], ga1 = g_gate[b * 2 + 1];
    const float gs  = g_gsum[b];

    const float* xb = x  + (size_t)b * NC * NHW + hw0;
    const float* sb = sh + (size_t)b * NC * NHW + hw0;

    // phase 0: stage x, shared, Wcat0
    stage_act(sX, xb, t);
    stage_act(sS, sb, t);
    stage_w_cat(sW, exp_w0 + (size_t)e0 * NR * NC, exp_w0 + (size_t)e1 * NR * NC, 1.f, t);
    __syncthreads();

    // GEMM1: accA = Wcat0 @ X
    float accA[2][8][4];
    #pragma unroll
    for (int i = 0; i < 2; ++i)
        #pragma unroll
        for (int j = 0; j < 8; ++j)
            #pragma unroll
            for (int kq = 0; kq < 4; ++kq) accA[i][j][kq] = 0.f;
    gemm_mma(sW, sX, accA, m0, n0, lane);
    __syncthreads();

    // phase 1: stage Wcat1
    stage_w_cat(sW, exp_w1 + (size_t)e0 * NR * NC, exp_w1 + (size_t)e1 * NR * NC, 1.f, t);
    __syncthreads();

    // GEMM2: accG = Wcat1 @ Sh
    float accG[2][8][4];
    #pragma unroll
    for (int i = 0; i < 2; ++i)
        #pragma unroll
        for (int j = 0; j < 8; ++j)
            #pragma unroll
            for (int kq = 0; kq < 4; ++kq) accG[i][j][kq] = 0.f;
    gemm_mma(sW, sS, accG, m0, n0, lane);
    __syncthreads();   // everyone done reading sS and sW

    // T = accA * silu(accG) -> sS (as tf32), row = rank, col = pixel
    {
        const int ar = lane >> 2, ac = lane & 3;
        #pragma unroll
        for (int mf = 0; mf < 2; ++mf) {
            #pragma unroll
            for (int nf = 0; nf < 8; ++nf) {
                const int col = n0 + nf * 8 + 2 * ac;
                #pragma unroll
                for (int half = 0; half < 2; ++half) {
                    const int row = m0 + mf * 16 + ar + half * 8;
                    float a0 = accA[mf][nf][half * 2 + 0];
                    float a1 = accA[mf][nf][half * 2 + 1];
                    float g0 = accG[mf][nf][half * 2 + 0];
                    float g1 = accG[mf][nf][half * 2 + 1];
                    uint2 w;
                    w.x = f2tf(a0 * (g0 / (1.f + __expf(-g0))));
                    w.y = f2tf(a1 * (g1 / (1.f + __expf(-g1))));
                    *(uint2*)(sS + row * LDX + col) = w;
                }
            }
        }
    }
    // stage Mcat while T is being written (separate smem region)
    stage_mcat(sW, g_PW2, e0, e1, ga0, ga1, t);
    __syncthreads();

    // GEMM3: accO = Mcat @ T
    float accO[2][8][4];
    #pragma unroll
    for (int i = 0; i < 2; ++i)
        #pragma unroll
        for (int j = 0; j < 8; ++j)
            #pragma unroll
            for (int kq = 0; kq < 4; ++kq) accO[i][j][kq] = 0.f;
    gemm_mma(sW, sS, accO, m0, n0, lane);
    __syncthreads();

    // phase 3: stage gs*proj
    stage_w_cat(sW, proj_w, proj_w + 64 * NC, gs, t);
    __syncthreads();

    // GEMM4: accO += (gs*proj) @ X
    gemm_mma(sW, sX, accO, m0, n0, lane);

    // epilogue
    {
        const int ar = lane >> 2, ac = lane & 3;
        float* ob = out + (size_t)b * NC * NHW + hw0;
        #pragma unroll
        for (int mf = 0; mf < 2; ++mf) {
            #pragma unroll
            for (int nf = 0; nf < 8; ++nf) {
                const int col = n0 + nf * 8 + 2 * ac;
                #pragma unroll
                for (int half = 0; half < 2; ++half) {
                    const int row = m0 + mf * 16 + ar + half * 8;
                    float2 v = make_float2(accO[mf][nf][half * 2 + 0],
                                           accO[mf][nf][half * 2 + 1]);
                    *(float2*)(ob + (size_t)row * NHW + col) = v;
                }
            }
        }
    }
}

// ---------------------------------------------------------------------------
extern "C" void kernel_launch(void* const* d_in, const int* in_sizes, int n_in,
                              void* d_out, int out_size) {
    const float* x       = (const float*)d_in[0];
    const float* sh      = (const float*)d_in[1];
    const float* mlp_w1  = (const float*)d_in[2];
    const float* mlp_b1  = (const float*)d_in[3];
    const float* mlp_w2  = (const float*)d_in[4];
    const float* mlp_b2  = (const float*)d_in[5];
    const float* gate_w  = (const float*)d_in[6];
    const float* fgate_w = (const float*)d_in[7];
    const float* exp_w0  = (const float*)d_in[8];
    const float* exp_w1  = (const float*)d_in[9];
    const float* exp_w2  = (const float*)d_in[10];
    const float* proj_w  = (const float*)d_in[11];
    float* out = (float*)d_out;

    cudaFuncSetAttribute(conv_pool_kernel, cudaFuncAttributeMaxDynamicSharedMemorySize, 65536);
    cudaFuncSetAttribute(main_mma_kernel, cudaFuncAttributeMaxDynamicSharedMemorySize, SMEM_MAIN);

    conv_pool_kernel<<<NB * NC, 256, 65536>>>(x);
    pw2_kernel<<<128, 256>>>(exp_w2, proj_w);
    routing_kernel<<<NB, 256>>>(mlp_w1, mlp_b1, mlp_w2, mlp_b2, gate_w, fgate_w);
    main_mma_kernel<<<dim3(NHW / 128, NB), 256, SMEM_MAIN>>>(x, sh, exp_w0, exp_w1, proj_w, out);
}

// round 4
// speedup vs baseline: 4.2022x; 1.0984x over previous
#include <cuda_runtime.h>
#include <math.h>
#include <stdint.h>

// Problem constants
#define NB 8
#define NC 128
#define NHW 16384
#define NE 4
#define NR 64

// smem layout (words) for main kernel
#define LDW 132           // weight tile ld  (conflict-free A-frag LDS)
#define LDX 136           // act tile ld     (conflict-free B-frag LDS)
#define SM_X 0
#define SM_S (128 * LDX)
#define SM_W (2 * 128 * LDX)
#define SMEM_MAIN ((2 * 128 * LDX + 128 * LDW) * 4)   // 206848 bytes

// ---------------- device scratch ----------------
__device__ float g_fe0[NB * NC];
__device__ float g_pooled[NB * NC];
__device__ int   g_sel[NB * 2];
__device__ float g_gate[NB * 2];
__device__ float g_gsum[NB];
__device__ float g_PW2[NE * NC * NR];   // proj_w @ exp_w2[e] : [e][d][r]

__device__ __forceinline__ float gelu_f(float v) {
    return 0.5f * v * (1.0f + erff(v * 0.70710678118654752440f));
}
// fast tanh-approx GELU (HW tanh); only used inside the 16K-point spatial mean,
// where its ~1e-3 max abs deviation from erf-GELU averages to ~1e-4 on fe0.
__device__ __forceinline__ float gelu_fast(float v) {
    float u = 0.7978845608f * (v + 0.044715f * v * v * v);
    float th;
    asm("tanh.approx.f32 %0, %1;" : "=f"(th) : "f"(u));
    return 0.5f * v * (1.0f + th);
}
__device__ __forceinline__ uint32_t f2tf(float f) {
    uint32_t r; asm("cvt.rna.tf32.f32 %0, %1;" : "=r"(r) : "f"(f)); return r;
}
__device__ __forceinline__ void mma_tf32(float* c, const uint32_t* a, const uint32_t* b) {
    asm volatile(
        "mma.sync.aligned.m16n8k8.row.col.f32.tf32.tf32.f32 "
        "{%0,%1,%2,%3}, {%4,%5,%6,%7}, {%8,%9}, {%0,%1,%2,%3};"
        : "+f"(c[0]), "+f"(c[1]), "+f"(c[2]), "+f"(c[3])
        : "r"(a[0]), "r"(a[1]), "r"(a[2]), "r"(a[3]), "r"(b[0]), "r"(b[1]));
}

// ---------------------------------------------------------------------------
// Kernel 1 (fused): blocks [0,1024): depthwise 3x3 high-pass -> GELU -> mean
//                   + raw mean.  blocks [1024,1152): PW2 = proj_w @ exp_w2[e].
// ---------------------------------------------------------------------------
__global__ __launch_bounds__(256) void conv_pw2_kernel(
    const float* __restrict__ x, const float* __restrict__ exp_w2,
    const float* __restrict__ proj_w) {
    if (blockIdx.x >= NB * NC) {
        // ---- PW2 part ----
        int bi = blockIdx.x - NB * NC;
        int e = bi >> 5;
        int d = ((bi & 31) << 2) + (threadIdx.x >> 6);
        int r = threadIdx.x & 63;
        const float* pw = proj_w + d * NC;
        const float* w2 = exp_w2 + (size_t)e * NC * NR + r;
        float a = 0.f;
        #pragma unroll 8
        for (int c = 0; c < NC; ++c) a += pw[c] * w2[c * NR];
        g_PW2[(e * NC + d) * NR + r] = a;
        return;
    }

    extern __shared__ float sp[];
    const int t = threadIdx.x;
    const float* xp = x + (size_t)blockIdx.x * NHW;

    float sumx = 0.f;
    #pragma unroll 4
    for (int i = 0; i < 16; ++i) {
        int i4 = t + (i << 8);
        float4 v = ((const float4*)xp)[i4];
        ((float4*)sp)[i4] = v;
        sumx += v.x + v.y + v.z + v.w;
    }
    __syncthreads();

    float sumg = 0.f;
    #pragma unroll 4
    for (int i = 0; i < 64; ++i) {
        int idx = t + (i << 8);
        int h = idx >> 7, w = idx & 127;
        float cen = sp[idx];
        float nb = 0.f;
        bool up = (h > 0), dn = (h < 127), lf = (w > 0), rt = (w < 127);
        if (up)        nb += sp[idx - 128];
        if (dn)        nb += sp[idx + 128];
        if (lf)        nb += sp[idx - 1];
        if (rt)        nb += sp[idx + 1];
        if (up && lf)  nb += sp[idx - 129];
        if (up && rt)  nb += sp[idx - 127];
        if (dn && lf)  nb += sp[idx + 127];
        if (dn && rt)  nb += sp[idx + 129];
        sumg += gelu_fast(8.f * cen - nb);
    }

    __shared__ float rx[8], rg[8];
    for (int o = 16; o > 0; o >>= 1) {
        sumx += __shfl_down_sync(0xffffffffu, sumx, o);
        sumg += __shfl_down_sync(0xffffffffu, sumg, o);
    }
    if ((t & 31) == 0) { rx[t >> 5] = sumx; rg[t >> 5] = sumg; }
    __syncthreads();
    if (t == 0) {
        float ax = 0.f, ag = 0.f;
        #pragma unroll
        for (int i = 0; i < 8; ++i) { ax += rx[i]; ag += rg[i]; }
        const float inv = 1.0f / 16384.0f;
        g_pooled[blockIdx.x] = ax * inv;
        g_fe0[blockIdx.x]   = ag * inv;
    }
}

// ---------------------------------------------------------------------------
// Kernel 2: routing, one block per batch
// ---------------------------------------------------------------------------
__global__ __launch_bounds__(256) void routing_kernel(
    const float* __restrict__ mlp_w1, const float* __restrict__ mlp_b1,
    const float* __restrict__ mlp_w2, const float* __restrict__ mlp_b2,
    const float* __restrict__ gate_w, const float* __restrict__ fgate_w) {
    __shared__ float s_in[NC], s_pool[NC], s_h1[256], s_fe[NC], s_log[NE];
    const int b = blockIdx.x;
    const int t = threadIdx.x;

    if (t < NC) { s_in[t] = g_fe0[b * NC + t]; s_pool[t] = g_pooled[b * NC + t]; }
    __syncthreads();

    {
        float a = mlp_b1[t];
        #pragma unroll 8
        for (int c = 0; c < NC; ++c) a += s_in[c] * mlp_w1[c * 256 + t];
        s_h1[t] = gelu_f(a);
    }
    __syncthreads();
    if (t < NC) {
        float a = mlp_b2[t];
        #pragma unroll 8
        for (int c = 0; c < 256; ++c) a += s_h1[c] * mlp_w2[c * NC + t];
        s_fe[t] = a;
    }
    __syncthreads();
    if (t < NE) {
        float a = 0.f;
        for (int c = 0; c < NC; ++c)
            a += s_pool[c] * gate_w[c * NE + t] + s_fe[c] * fgate_w[c * NE + t];
        s_log[t] = a;
    }
    __syncthreads();
    if (t == 0) {
        float sc[NE];
        float m = -1e30f;
        #pragma unroll
        for (int e = 0; e < NE; ++e) { sc[e] = s_log[e]; m = fmaxf(m, sc[e]); }
        float ss = 0.f;
        #pragma unroll
        for (int e = 0; e < NE; ++e) { sc[e] = expf(sc[e] - m); ss += sc[e]; }
        float inv = 1.0f / ss;
        #pragma unroll
        for (int e = 0; e < NE; ++e) sc[e] *= inv;
        int i0 = 0;
        #pragma unroll
        for (int e = 1; e < NE; ++e) if (sc[e] > sc[i0]) i0 = e;
        int i1 = -1;
        #pragma unroll
        for (int e = 0; e < NE; ++e) {
            if (e == i0) continue;
            if (i1 < 0 || sc[e] > sc[i1]) i1 = e;
        }
        g_sel[b * 2] = i0;  g_sel[b * 2 + 1] = i1;
        g_gate[b * 2] = sc[i0]; g_gate[b * 2 + 1] = sc[i1];
        g_gsum[b] = sc[i0] + sc[i1];
    }
}

// ---------------------------------------------------------------------------
// Main tensor-core kernel (mma.sync tf32) with register-prefetch pipelining.
// ---------------------------------------------------------------------------

// initial (non-pipelined) stage of a [128m][128k] weight tile (rows 0..63 from
// a, 64..127 from b2)
__device__ __forceinline__ void stage_w_cat(uint32_t* sW, const float* __restrict__ a,
                                            const float* __restrict__ b2, int t) {
    const int q = t & 31, r0 = t >> 5;
    #pragma unroll
    for (int i = 0; i < 16; ++i) {
        int row = r0 + 8 * i;
        const float* src = (i < 8) ? (a + row * 128) : (b2 + (row - 64) * 128);
        float4 u = *(const float4*)(src + q * 4);
        uint4 w;
        w.x = f2tf(u.x); w.y = f2tf(u.y); w.z = f2tf(u.z); w.w = f2tf(u.w);
        *(uint4*)(sW + row * LDW + q * 4) = w;
    }
}

// prefetch a weight-cat tile into registers (16 float4 per thread)
__device__ __forceinline__ void prefetch_cat(float4* pf, const float* __restrict__ a,
                                             const float* __restrict__ b2, int t) {
    const int q = t & 31, r0 = t >> 5;
    #pragma unroll
    for (int i = 0; i < 16; ++i) {
        int row = r0 + 8 * i;
        const float* src = (i < 8) ? (a + row * 128) : (b2 + (row - 64) * 128);
        pf[i] = *(const float4*)(src + q * 4);
    }
}

// prefetch Mcat sources: row=d, cols q*4.. ; q<16 -> PW2[e0][d][q*4], else e1
__device__ __forceinline__ void prefetch_mcat(float4* pf, const float* __restrict__ pw2,
                                              int e0, int e1, int t) {
    const int q = t & 31, r0 = t >> 5;
    const float* base = (q < 16) ? (pw2 + (size_t)e0 * NC * NR + q * 4)
                                 : (pw2 + (size_t)e1 * NC * NR + (q - 16) * 4);
    #pragma unroll
    for (int i = 0; i < 16; ++i) {
        int d = r0 + 8 * i;
        pf[i] = *(const float4*)(base + d * NR);
    }
}

// write prefetched tile to sW with scale + tf32 convert
__device__ __forceinline__ void sts_cat(uint32_t* sW, const float4* pf, float sc, int t) {
    const int q = t & 31, r0 = t >> 5;
    #pragma unroll
    for (int i = 0; i < 16; ++i) {
        int row = r0 + 8 * i;
        uint4 w;
        w.x = f2tf(pf[i].x * sc); w.y = f2tf(pf[i].y * sc);
        w.z = f2tf(pf[i].z * sc); w.w = f2tf(pf[i].w * sc);
        *(uint4*)(sW + row * LDW + q * 4) = w;
    }
}

// stage [128k][128n] activation tile (k = channel, n = pixel)
__device__ __forceinline__ void stage_act(uint32_t* sA, const float* __restrict__ gsrc, int t) {
    #pragma unroll
    for (int f = t; f < 4096; f += 256) {
        int c = f >> 5, q = f & 31;
        float4 u = *(const float4*)(gsrc + (size_t)c * NHW + q * 4);
        uint4 w;
        w.x = f2tf(u.x); w.y = f2tf(u.y); w.z = f2tf(u.z); w.w = f2tf(u.w);
        *(uint4*)(sA + c * LDX + q * 4) = w;
    }
}

// acc[mf][nf][4] += sW[m0+.., k] * sB[k, n0+..]   (M=32, N=64, K=128)
__device__ __forceinline__ void gemm_mma(const uint32_t* __restrict__ sW,
                                         const uint32_t* __restrict__ sB,
                                         float acc[2][8][4], int m0, int n0, int lane) {
    const int ar = lane >> 2, ac = lane & 3;
    #pragma unroll
    for (int kk = 0; kk < 16; ++kk) {
        const int k0 = kk << 3;
        uint32_t a[2][4];
        #pragma unroll
        for (int mf = 0; mf < 2; ++mf) {
            const uint32_t* pa = sW + (m0 + mf * 16 + ar) * LDW + k0 + ac;
            a[mf][0] = pa[0];
            a[mf][2] = pa[4];
            a[mf][1] = pa[8 * LDW];
            a[mf][3] = pa[8 * LDW + 4];
        }
        #pragma unroll
        for (int nf = 0; nf < 8; ++nf) {
            const uint32_t* pb = sB + (k0 + ac) * LDX + n0 + nf * 8 + ar;
            uint32_t b[2];
            b[0] = pb[0];
            b[1] = pb[4 * LDX];
            mma_tf32(acc[0][nf], a[0], b);
            mma_tf32(acc[1][nf], a[1], b);
        }
    }
}

__global__ __launch_bounds__(256, 1) void main_mma_kernel(
    const float* __restrict__ x, const float* __restrict__ sh,
    const float* __restrict__ exp_w0, const float* __restrict__ exp_w1,
    const float* __restrict__ proj_w, float* __restrict__ out) {
    extern __shared__ uint32_t smem[];
    uint32_t* sX = smem + SM_X;
    uint32_t* sS = smem + SM_S;     // later reused for T
    uint32_t* sW = smem + SM_W;

    const int t = threadIdx.x;
    const int lane = t & 31;
    const int wid = t >> 5;
    const int m0 = (wid >> 1) << 5;          // 0,32,64,96
    const int n0 = (wid & 1) << 6;           // 0,64
    const int b = blockIdx.y;
    const int hw0 = blockIdx.x * 128;

    const int   e0  = g_sel[b * 2],  e1  = g_sel[b * 2 + 1];
    const float ga0 = g_gate[b * 2], ga1 = g_gate[b * 2 + 1];
    const float gs  = g_gsum[b];

    const float* xb = x  + (size_t)b * NC * NHW + hw0;
    const float* sb = sh + (size_t)b * NC * NHW + hw0;

    // phase 0: stage x, shared, Wcat0
    stage_act(sX, xb, t);
    stage_act(sS, sb, t);
    stage_w_cat(sW, exp_w0 + (size_t)e0 * NR * NC, exp_w0 + (size_t)e1 * NR * NC, t);
    __syncthreads();

    // prefetch Wcat1 while GEMM1 runs
    float4 pf[16];
    prefetch_cat(pf, exp_w1 + (size_t)e0 * NR * NC, exp_w1 + (size_t)e1 * NR * NC, t);

    // GEMM1: accA = Wcat0 @ X
    float accA[2][8][4];
    #pragma unroll
    for (int i = 0; i < 2; ++i)
        #pragma unroll
        for (int j = 0; j < 8; ++j)
            #pragma unroll
            for (int kq = 0; kq < 4; ++kq) accA[i][j][kq] = 0.f;
    gemm_mma(sW, sX, accA, m0, n0, lane);
    __syncthreads();           // everyone done reading sW(W0)

    sts_cat(sW, pf, 1.f, t);   // W1 -> sW
    __syncthreads();

    // prefetch Mcat sources while GEMM2 runs
    prefetch_mcat(pf, g_PW2, e0, e1, t);

    // GEMM2: accG = Wcat1 @ Sh
    float accG[2][8][4];
    #pragma unroll
    for (int i = 0; i < 2; ++i)
        #pragma unroll
        for (int j = 0; j < 8; ++j)
            #pragma unroll
            for (int kq = 0; kq < 4; ++kq) accG[i][j][kq] = 0.f;
    gemm_mma(sW, sS, accG, m0, n0, lane);
    __syncthreads();           // done reading sS and sW

    // T = accA * silu(accG) -> sS (tf32); Mcat (gated) -> sW
    {
        const int ar = lane >> 2, ac = lane & 3;
        #pragma unroll
        for (int mf = 0; mf < 2; ++mf) {
            #pragma unroll
            for (int nf = 0; nf < 8; ++nf) {
                const int col = n0 + nf * 8 + 2 * ac;
                #pragma unroll
                for (int half = 0; half < 2; ++half) {
                    const int row = m0 + mf * 16 + ar + half * 8;
                    float a0 = accA[mf][nf][half * 2 + 0];
                    float a1 = accA[mf][nf][half * 2 + 1];
                    float g0 = accG[mf][nf][half * 2 + 0];
                    float g1 = accG[mf][nf][half * 2 + 1];
                    uint2 w;
                    w.x = f2tf(a0 * (g0 / (1.f + __expf(-g0))));
                    w.y = f2tf(a1 * (g1 / (1.f + __expf(-g1))));
                    *(uint2*)(sS + row * LDX + col) = w;
                }
            }
        }
    }
    {
        const float msc = ((t & 31) < 16) ? ga0 : ga1;   // col-half gate scale
        sts_cat(sW, pf, msc, t);
    }
    __syncthreads();

    // prefetch proj while GEMM3 runs
    prefetch_cat(pf, proj_w, proj_w + 64 * NC, t);

    // GEMM3: accO = Mcat @ T
    float accO[2][8][4];
    #pragma unroll
    for (int i = 0; i < 2; ++i)
        #pragma unroll
        for (int j = 0; j < 8; ++j)
            #pragma unroll
            for (int kq = 0; kq < 4; ++kq) accO[i][j][kq] = 0.f;
    gemm_mma(sW, sS, accO, m0, n0, lane);
    __syncthreads();

    sts_cat(sW, pf, gs, t);    // gs*proj -> sW
    __syncthreads();

    // GEMM4: accO += (gs*proj) @ X
    gemm_mma(sW, sX, accO, m0, n0, lane);

    // epilogue
    {
        const int ar = lane >> 2, ac = lane & 3;
        float* ob = out + (size_t)b * NC * NHW + hw0;
        #pragma unroll
        for (int mf = 0; mf < 2; ++mf) {
            #pragma unroll
            for (int nf = 0; nf < 8; ++nf) {
                const int col = n0 + nf * 8 + 2 * ac;
                #pragma unroll
                for (int half = 0; half < 2; ++half) {
                    const int row = m0 + mf * 16 + ar + half * 8;
                    float2 v = make_float2(accO[mf][nf][half * 2 + 0],
                                           accO[mf][nf][half * 2 + 1]);
                    *(float2*)(ob + (size_t)row * NHW + col) = v;
                }
            }
        }
    }
}

// ---------------------------------------------------------------------------
extern "C" void kernel_launch(void* const* d_in, const int* in_sizes, int n_in,
                              void* d_out, int out_size) {
    const float* x       = (const float*)d_in[0];
    const float* sh      = (const float*)d_in[1];
    const float* mlp_w1  = (const float*)d_in[2];
    const float* mlp_b1  = (const float*)d_in[3];
    const float* mlp_w2  = (const float*)d_in[4];
    const float* mlp_b2  = (const float*)d_in[5];
    const float* gate_w  = (const float*)d_in[6];
    const float* fgate_w = (const float*)d_in[7];
    const float* exp_w0  = (const float*)d_in[8];
    const float* exp_w1  = (const float*)d_in[9];
    const float* exp_w2  = (const float*)d_in[10];
    const float* proj_w  = (const float*)d_in[11];
    float* out = (float*)d_out;

    cudaFuncSetAttribute(conv_pw2_kernel, cudaFuncAttributeMaxDynamicSharedMemorySize, 65536);
    cudaFuncSetAttribute(main_mma_kernel, cudaFuncAttributeMaxDynamicSharedMemorySize, SMEM_MAIN);

    conv_pw2_kernel<<<NB * NC + 128, 256, 65536>>>(x, exp_w2, proj_w);
    routing_kernel<<<NB, 256>>>(mlp_w1, mlp_b1, mlp_w2, mlp_b2, gate_w, fgate_w);
    main_mma_kernel<<<dim3(NHW / 128, NB), 256, SMEM_MAIN>>>(x, sh, exp_w0, exp_w1, proj_w, out);
}